// round 4
// baseline (speedup 1.0000x reference)
#include <cuda_runtime.h>
#include <cstdint>

#define NPTS 400000
#define CCH  32
#define SX   480
#define SY   360
#define SZ   32
#define BB   2
#define LOOKUP_SIZE (BB*SX*SY*SZ)
#define EPSV 1e-5f

// ---- static scratch (no allocations allowed) ----
__device__ int   d_lookup[LOOKUP_SIZE];          // cell -> idx+1, 0 = empty (persistent)
__device__ __align__(16) float d_sums[64];       // [0:32) sum, [32:64) sumsq
__device__ float d_scale[CCH];
__device__ float d_shift[CCH];
__device__ int   d_cnt[8];                       // per-k pair counts (k != 4)
__device__ int2  d_pairs[8][NPTS];               // (out_pt, in_pt) per k
__device__ unsigned char d_flag[NPTS];           // point has >=1 valid neighbor

// ---- packed fp32x2 helpers ----
#define FMA2(d, a, b, c) \
    asm("fma.rn.f32x2 %0, %1, %2, %3;" : "=l"(d) : "l"(a), "l"(b), "l"(c))
#define PACK2(d, x) \
    asm("mov.b64 %0, {%1, %1};" : "=l"(d) : "r"(__float_as_uint(x)))
#define UNPACK2(lo, hi, a) \
    asm("mov.b64 {%0, %1}, %2;" : "=r"(lo), "=r"(hi) : "l"(a))

// ============================================================
// GEMV core: acc[16] (f32x2 pairs over 32 couts) += feat_row @ W(smem)
// ============================================================
__device__ __forceinline__ void gemv_accum(
    const float* __restrict__ frow,
    const unsigned long long* __restrict__ wbase,
    unsigned long long acc[16])
{
    const float4* fr = (const float4*)frow;
    float4 f0 = __ldg(fr + 0), f1 = __ldg(fr + 1);
    float4 f2 = __ldg(fr + 2), f3 = __ldg(fr + 3);
    float4 f4 = __ldg(fr + 4), f5 = __ldg(fr + 5);
    float4 f6 = __ldg(fr + 6), f7 = __ldg(fr + 7);
    float fv[32] = {
        f0.x, f0.y, f0.z, f0.w, f1.x, f1.y, f1.z, f1.w,
        f2.x, f2.y, f2.z, f2.w, f3.x, f3.y, f3.z, f3.w,
        f4.x, f4.y, f4.z, f4.w, f5.x, f5.y, f5.z, f5.w,
        f6.x, f6.y, f6.z, f6.w, f7.x, f7.y, f7.z, f7.w };
#pragma unroll
    for (int cin = 0; cin < 32; cin++) {
        unsigned long long bc;
        PACK2(bc, fv[cin]);
        const ulonglong2* wv = (const ulonglong2*)(wbase + cin * 16);
#pragma unroll
        for (int h = 0; h < 8; h++) {
            ulonglong2 wp = wv[h];
            FMA2(acc[2 * h],     bc, wp.x, acc[2 * h]);
            FMA2(acc[2 * h + 1], bc, wp.y, acc[2 * h + 1]);
        }
    }
}

// ============================================================
// 1. prep: reset pair counters + scatter lookup (no bulk zero)
// ============================================================
__global__ void prep_kernel(const int4* __restrict__ coords) {
    int i = blockIdx.x * blockDim.x + threadIdx.x;
    if (i < 8) d_cnt[i] = 0;
    if (i < NPTS) {
        int4 c = coords[i];
        d_lookup[((c.x * SX + c.y) * SY + c.z) * SZ + c.w] = i + 1;
    }
}

// ============================================================
// 2. probe: build per-k pair lists, flag neighbored points,
//    zero ONLY the out rows that will receive red.adds (~25%)
// ============================================================
__global__ __launch_bounds__(256) void probe_kernel(const int4* __restrict__ coords,
                                                    float4* __restrict__ out4) {
    __shared__ int s_wcnt[8][8];
    __shared__ int s_wbase[8][8];
    int tid  = threadIdx.x;
    int lane = tid & 31;
    int warp = tid >> 5;
    int pt = blockIdx.x * 256 + tid;
    bool act = pt < NPTS;

    int4 cc = act ? coords[pt] : make_int4(0, 1, 0, 1);
    int base = ((cc.x * SX + cc.y) * SY + cc.z) * SZ + cc.w;

    unsigned mask = 0;
    int nb[8];
#pragma unroll
    for (int k = 0; k < 9; k++) {
        if (k == 4) continue;
        int d0 = k / 3 - 1, d2 = k % 3 - 1;
        int n0 = cc.y + d0, n2 = cc.w + d2;
        bool valid = act && (n0 >= 0) && (n0 < SX) && (n2 >= 0) && (n2 < SZ);
        int idx = valid ? (base + d0 * (SY * SZ) + d2) : 0;
        int j = valid ? __ldg(&d_lookup[idx]) : 0;
        int ki = (k < 4) ? k : k - 1;
        nb[ki] = j - 1;
        if (j > 0) mask |= (1u << ki);
    }

    if (act) {
        d_flag[pt] = (unsigned char)(mask ? 1 : 0);
        if (mask) {
            float4 z = make_float4(0.f, 0.f, 0.f, 0.f);
            float4* orow = out4 + pt * 8;
#pragma unroll
            for (int h = 0; h < 8; h++) orow[h] = z;
        }
    }

    unsigned bal[8];
#pragma unroll
    for (int ki = 0; ki < 8; ki++)
        bal[ki] = __ballot_sync(0xffffffffu, (mask >> ki) & 1u);
    if (lane == 0) {
#pragma unroll
        for (int ki = 0; ki < 8; ki++)
            s_wcnt[ki][warp] = __popc(bal[ki]);
    }
    __syncthreads();
    if (tid < 8) {
        int run = 0;
#pragma unroll
        for (int w = 0; w < 8; w++) {
            int c = s_wcnt[tid][w];
            s_wbase[tid][w] = run;
            run += c;
        }
        int g = atomicAdd(&d_cnt[tid], run);
#pragma unroll
        for (int w = 0; w < 8; w++)
            s_wbase[tid][w] += g;
    }
    __syncthreads();
#pragma unroll
    for (int ki = 0; ki < 8; ki++) {
        if ((mask >> ki) & 1u) {
            int rank = __popc(bal[ki] & ((1u << lane) - 1u));
            d_pairs[ki][s_wbase[ki][warp] + rank] = make_int2(pt, nb[ki]);
        }
    }
}

// ============================================================
// 3. neighbor conv: grid.y = ki, one thread per pair, uniform-k
// ============================================================
__global__ __launch_bounds__(256) void neighbor_kernel(
    const float* __restrict__ feat,
    const float* __restrict__ weight,
    float*       __restrict__ out)
{
    int ki = blockIdx.y;
    int k  = (ki < 4) ? ki : ki + 1;
    __shared__ unsigned long long w2[512];
    {
        const unsigned long long* ws =
            (const unsigned long long*)(weight + k * 1024);
        for (int i = threadIdx.x; i < 512; i += 256)
            w2[i] = ws[i];
    }
    __syncthreads();

    int n = d_cnt[ki];
    for (int p = blockIdx.x * 256 + threadIdx.x; p < n; p += gridDim.x * 256) {
        int2 pr = d_pairs[ki][p];
        unsigned long long acc[16];
#pragma unroll
        for (int q = 0; q < 16; q++) acc[q] = 0ull;
        gemv_accum(feat + (long long)pr.y * CCH, w2, acc);

        float* orow = out + (long long)pr.x * CCH;
#pragma unroll
        for (int h = 0; h < 8; h++) {
            unsigned int u0, u1, u2, u3;
            UNPACK2(u0, u1, acc[2 * h]);
            UNPACK2(u2, u3, acc[2 * h + 1]);
            asm volatile("red.global.add.v4.f32 [%0], {%1, %2, %3, %4};"
                         :: "l"(orow + 4 * h),
                            "f"(__uint_as_float(u0)), "f"(__uint_as_float(u1)),
                            "f"(__uint_as_float(u2)), "f"(__uint_as_float(u3))
                         : "memory");
        }
    }
}

// ============================================================
// 4. self conv + conditional partial add + LeakyReLU + BN reduce
//    BN reduce via warp shuffle butterfly (no smem transpose)
// ============================================================
__global__ __launch_bounds__(256, 2) void selfleaky_kernel(
    const float* __restrict__ feat,
    const float* __restrict__ weight,
    float*       __restrict__ out)
{
    __shared__ unsigned long long w2[512];
    __shared__ float s_sum[32], s_sq[32];
    {
        const unsigned long long* ws =
            (const unsigned long long*)(weight + 4 * 1024);
        for (int i = threadIdx.x; i < 512; i += 256)
            w2[i] = ws[i];
        if (threadIdx.x < 32) {
            s_sum[threadIdx.x] = 0.0f;
            s_sq[threadIdx.x]  = 0.0f;
        }
    }
    __syncthreads();

    int tid  = threadIdx.x;
    int lane = tid & 31;
    int pt = blockIdx.x * 256 + tid;
    bool act = pt < NPTS;

    unsigned long long acc[16];
#pragma unroll
    for (int q = 0; q < 16; q++) acc[q] = 0ull;
    if (act)
        gemv_accum(feat + (long long)pt * CCH, w2, acc);

    float a[32];
#pragma unroll
    for (int h = 0; h < 16; h++) {
        unsigned int u0, u1;
        UNPACK2(u0, u1, acc[h]);
        a[2 * h]     = __uint_as_float(u0);
        a[2 * h + 1] = __uint_as_float(u1);
    }

    // add neighbor partials only where they exist (~25% of points)
    if (act && d_flag[pt]) {
        const float4* prow = (const float4*)(out + (long long)pt * CCH);
#pragma unroll
        for (int h = 0; h < 8; h++) {
            float4 p = __ldg(prow + h);
            a[4 * h + 0] += p.x;
            a[4 * h + 1] += p.y;
            a[4 * h + 2] += p.z;
            a[4 * h + 3] += p.w;
        }
    }

#pragma unroll
    for (int i = 0; i < 32; i++)
        a[i] = fmaxf(a[i], 0.01f * a[i]);

    if (act) {
        float4* orow = (float4*)(out + (long long)pt * CCH);
#pragma unroll
        for (int h = 0; h < 8; h++)
            orow[h] = make_float4(a[4*h], a[4*h+1], a[4*h+2], a[4*h+3]);
    }

    // inactive threads contribute exact zeros (acc=0, no partial, leaky(0)=0)
    float b[32];
#pragma unroll
    for (int i = 0; i < 32; i++) b[i] = a[i] * a[i];

    // butterfly: after 5 stages, lane l holds warp-sum of channel l in slot 0
#pragma unroll
    for (int off = 16; off >= 1; off >>= 1) {
        bool hi = (lane & off) != 0;
#pragma unroll
        for (int i = 0; i < off; i++) {
            float sa = hi ? a[i] : a[i + off];
            float sb = hi ? b[i] : b[i + off];
            float ra = __shfl_xor_sync(0xffffffffu, sa, off);
            float rb = __shfl_xor_sync(0xffffffffu, sb, off);
            float ka = hi ? a[i + off] : a[i];
            float kb = hi ? b[i + off] : b[i];
            a[i] = ka + ra;
            b[i] = kb + rb;
        }
    }

    atomicAdd(&s_sum[lane], a[0]);
    atomicAdd(&s_sq[lane],  b[0]);
    __syncthreads();
    if (tid < 32) {
        atomicAdd(&d_sums[tid],      s_sum[tid]);
        atomicAdd(&d_sums[32 + tid], s_sq[tid]);
    }
}

// ============================================================
// 5. finalize: scale/shift, re-zero accumulators for next replay
// ============================================================
__global__ void finalize_kernel(const float* __restrict__ gamma,
                                const float* __restrict__ beta) {
    int c = threadIdx.x;
    if (c < CCH) {
        const float invN = 1.0f / (float)NPTS;
        float mean = d_sums[c] * invN;
        float var  = d_sums[32 + c] * invN - mean * mean;
        float sc   = gamma[c] * rsqrtf(var + EPSV);
        d_scale[c] = sc;
        d_shift[c] = beta[c] - mean * sc;
        d_sums[c] = 0.0f;
        d_sums[32 + c] = 0.0f;
    }
}

// ============================================================
// 6. normalize: one thread per row, 8 loads in flight
// ============================================================
__global__ __launch_bounds__(256) void norm_kernel(float4* __restrict__ y) {
    __shared__ float4 s_sc[8], s_sh[8];
    if (threadIdx.x < 8) {
        s_sc[threadIdx.x] = ((const float4*)d_scale)[threadIdx.x];
        s_sh[threadIdx.x] = ((const float4*)d_shift)[threadIdx.x];
    }
    __syncthreads();
    int pt = blockIdx.x * 256 + threadIdx.x;
    if (pt >= NPTS) return;
    float4* row = y + pt * 8;
    float4 v[8];
#pragma unroll
    for (int h = 0; h < 8; h++) v[h] = row[h];
#pragma unroll
    for (int h = 0; h < 8; h++) {
        float4 sc = s_sc[h], sh = s_sh[h];
        v[h].x = fmaf(v[h].x, sc.x, sh.x);
        v[h].y = fmaf(v[h].y, sc.y, sh.y);
        v[h].z = fmaf(v[h].z, sc.z, sh.z);
        v[h].w = fmaf(v[h].w, sc.w, sh.w);
        row[h] = v[h];
    }
}

// ============================================================
extern "C" void kernel_launch(void* const* d_in, const int* in_sizes, int n_in,
                              void* d_out, int out_size) {
    const float* feat   = (const float*)d_in[0];
    const int4*  coords = (const int4*)d_in[1];
    const float* weight = (const float*)d_in[2];
    const float* gamma  = (const float*)d_in[3];
    const float* beta   = (const float*)d_in[4];
    float* out = (float*)d_out;

    prep_kernel<<<(NPTS + 255) / 256, 256>>>(coords);
    probe_kernel<<<(NPTS + 255) / 256, 256>>>(coords, (float4*)out);
    neighbor_kernel<<<dim3(64, 8), 256>>>(feat, weight, out);
    selfleaky_kernel<<<(NPTS + 255) / 256, 256>>>(feat, weight, out);
    finalize_kernel<<<1, 32>>>(gamma, beta);
    norm_kernel<<<(NPTS + 255) / 256, 256>>>((float4*)out);
}

// round 5
// speedup vs baseline: 1.3443x; 1.3443x over previous
#include <cuda_runtime.h>
#include <cstdint>

#define NPTS 400000
#define CCH  32
#define SX   480
#define SY   360
#define SZ   32
#define BB   2
#define LOOKUP_SIZE (BB*SX*SY*SZ)
#define EPSV 1e-5f

// ---- static scratch (no allocations allowed) ----
__device__ int   d_lookup[LOOKUP_SIZE];          // cell -> idx+1, 0 = empty (persistent)
__device__ __align__(16) float d_sums[64];       // [0:32) sum, [32:64) sumsq
__device__ float d_scale[CCH];
__device__ float d_shift[CCH];
__device__ int   d_cnt[8];                       // per-k pair counts (k != 4)
__device__ int2  d_pairs[8][NPTS];               // (out_pt, in_pt) per k
__device__ unsigned char d_flag[NPTS];           // point has >=1 valid neighbor

// ---- packed fp32x2 helpers ----
#define FMA2(d, a, b, c) \
    asm("fma.rn.f32x2 %0, %1, %2, %3;" : "=l"(d) : "l"(a), "l"(b), "l"(c))
#define PACK2(d, x) \
    asm("mov.b64 %0, {%1, %1};" : "=l"(d) : "r"(__float_as_uint(x)))
#define UNPACK2(lo, hi, a) \
    asm("mov.b64 {%0, %1}, %2;" : "=r"(lo), "=r"(hi) : "l"(a))

// ============================================================
// GEMV core from global feat row (used by neighbor kernel)
// ============================================================
__device__ __forceinline__ void gemv_accum(
    const float* __restrict__ frow,
    const unsigned long long* __restrict__ wbase,
    unsigned long long acc[16])
{
    const float4* fr = (const float4*)frow;
    float4 f0 = __ldg(fr + 0), f1 = __ldg(fr + 1);
    float4 f2 = __ldg(fr + 2), f3 = __ldg(fr + 3);
    float4 f4 = __ldg(fr + 4), f5 = __ldg(fr + 5);
    float4 f6 = __ldg(fr + 6), f7 = __ldg(fr + 7);
    float fv[32] = {
        f0.x, f0.y, f0.z, f0.w, f1.x, f1.y, f1.z, f1.w,
        f2.x, f2.y, f2.z, f2.w, f3.x, f3.y, f3.z, f3.w,
        f4.x, f4.y, f4.z, f4.w, f5.x, f5.y, f5.z, f5.w,
        f6.x, f6.y, f6.z, f6.w, f7.x, f7.y, f7.z, f7.w };
#pragma unroll
    for (int cin = 0; cin < 32; cin++) {
        unsigned long long bc;
        PACK2(bc, fv[cin]);
        const ulonglong2* wv = (const ulonglong2*)(wbase + cin * 16);
#pragma unroll
        for (int h = 0; h < 8; h++) {
            ulonglong2 wp = wv[h];
            FMA2(acc[2 * h],     bc, wp.x, acc[2 * h]);
            FMA2(acc[2 * h + 1], bc, wp.y, acc[2 * h + 1]);
        }
    }
}

// ============================================================
// 1. prep: bulk-zero out buffer, reset counters, scatter lookup
// ============================================================
__global__ void prep_kernel(const int4* __restrict__ coords,
                            float4* __restrict__ out4) {
    int i = blockIdx.x * blockDim.x + threadIdx.x;
    if (i < 8) d_cnt[i] = 0;
    const int total4 = NPTS * 8;
    float4 z = make_float4(0.f, 0.f, 0.f, 0.f);
    for (int t = i; t < total4; t += gridDim.x * blockDim.x)
        out4[t] = z;
    if (i < NPTS) {
        int4 c = coords[i];
        d_lookup[((c.x * SX + c.y) * SY + c.z) * SZ + c.w] = i + 1;
    }
}

// ============================================================
// 2. probe: per-k pair lists + has-neighbor flag
// ============================================================
__global__ __launch_bounds__(256) void probe_kernel(const int4* __restrict__ coords) {
    __shared__ int s_wcnt[8][8];
    __shared__ int s_wbase[8][8];
    int tid  = threadIdx.x;
    int lane = tid & 31;
    int warp = tid >> 5;
    int pt = blockIdx.x * 256 + tid;
    bool act = pt < NPTS;

    int4 cc = act ? coords[pt] : make_int4(0, 1, 0, 1);
    int base = ((cc.x * SX + cc.y) * SY + cc.z) * SZ + cc.w;

    unsigned mask = 0;
    int nb[8];
#pragma unroll
    for (int k = 0; k < 9; k++) {
        if (k == 4) continue;
        int d0 = k / 3 - 1, d2 = k % 3 - 1;
        int n0 = cc.y + d0, n2 = cc.w + d2;
        bool valid = act && (n0 >= 0) && (n0 < SX) && (n2 >= 0) && (n2 < SZ);
        int idx = valid ? (base + d0 * (SY * SZ) + d2) : 0;
        int j = valid ? __ldg(&d_lookup[idx]) : 0;
        int ki = (k < 4) ? k : k - 1;
        nb[ki] = j - 1;
        if (j > 0) mask |= (1u << ki);
    }

    if (act) d_flag[pt] = (unsigned char)(mask ? 1 : 0);

    unsigned bal[8];
#pragma unroll
    for (int ki = 0; ki < 8; ki++)
        bal[ki] = __ballot_sync(0xffffffffu, (mask >> ki) & 1u);
    if (lane == 0) {
#pragma unroll
        for (int ki = 0; ki < 8; ki++)
            s_wcnt[ki][warp] = __popc(bal[ki]);
    }
    __syncthreads();
    if (tid < 8) {
        int run = 0;
#pragma unroll
        for (int w = 0; w < 8; w++) {
            int c = s_wcnt[tid][w];
            s_wbase[tid][w] = run;
            run += c;
        }
        int g = atomicAdd(&d_cnt[tid], run);
#pragma unroll
        for (int w = 0; w < 8; w++)
            s_wbase[tid][w] += g;
    }
    __syncthreads();
#pragma unroll
    for (int ki = 0; ki < 8; ki++) {
        if ((mask >> ki) & 1u) {
            int rank = __popc(bal[ki] & ((1u << lane) - 1u));
            d_pairs[ki][s_wbase[ki][warp] + rank] = make_int2(pt, nb[ki]);
        }
    }
}

// ============================================================
// 3. neighbor conv: grid.y = ki, one thread per pair, uniform-k
// ============================================================
__global__ __launch_bounds__(256) void neighbor_kernel(
    const float* __restrict__ feat,
    const float* __restrict__ weight,
    float*       __restrict__ out)
{
    int ki = blockIdx.y;
    int k  = (ki < 4) ? ki : ki + 1;
    __shared__ unsigned long long w2[512];
    {
        const unsigned long long* ws =
            (const unsigned long long*)(weight + k * 1024);
        for (int i = threadIdx.x; i < 512; i += 256)
            w2[i] = ws[i];
    }
    __syncthreads();

    int n = d_cnt[ki];
    for (int p = blockIdx.x * 256 + threadIdx.x; p < n; p += gridDim.x * 256) {
        int2 pr = d_pairs[ki][p];
        unsigned long long acc[16];
#pragma unroll
        for (int q = 0; q < 16; q++) acc[q] = 0ull;
        gemv_accum(feat + (long long)pr.y * CCH, w2, acc);

        float* orow = out + (long long)pr.x * CCH;
#pragma unroll
        for (int h = 0; h < 8; h++) {
            unsigned int u0, u1, u2, u3;
            UNPACK2(u0, u1, acc[2 * h]);
            UNPACK2(u2, u3, acc[2 * h + 1]);
            asm volatile("red.global.add.v4.f32 [%0], {%1, %2, %3, %4};"
                         :: "l"(orow + 4 * h),
                            "f"(__uint_as_float(u0)), "f"(__uint_as_float(u1)),
                            "f"(__uint_as_float(u2)), "f"(__uint_as_float(u3))
                         : "memory");
        }
    }
}

// ============================================================
// 4. self conv + partial add + LeakyReLU + BN reduce
//    coalesced global IO via padded smem staging (stride 33 floats)
// ============================================================
#define RSTR 33
__global__ __launch_bounds__(256, 2) void selfleaky_kernel(
    const float* __restrict__ feat,
    const float* __restrict__ weight,
    float*       __restrict__ out)
{
    __shared__ unsigned long long w2[512];       // 4 KB weights (k=4)
    __shared__ float s_rows[256 * RSTR];         // 33 KB staging
    __shared__ float s_sum[32], s_sq[32];
    {
        const unsigned long long* ws =
            (const unsigned long long*)(weight + 4 * 1024);
        for (int i = threadIdx.x; i < 512; i += 256)
            w2[i] = ws[i];
        if (threadIdx.x < 32) {
            s_sum[threadIdx.x] = 0.0f;
            s_sq[threadIdx.x]  = 0.0f;
        }
    }

    int tid  = threadIdx.x;
    int lane = tid & 31;
    int blk0 = blockIdx.x * 256;            // first point of block
    int pt   = blk0 + tid;
    bool act = pt < NPTS;

    // ---- stage 256 feature rows, coalesced ----
    {
        const float4* f4 = (const float4*)feat;
        int gbase = blk0 * 8;
#pragma unroll
        for (int i = 0; i < 8; i++) {
            int g = gbase + i * 256 + tid;
            float4 v = (g < NPTS * 8) ? __ldg(f4 + g)
                                      : make_float4(0.f, 0.f, 0.f, 0.f);
            int r = (i * 256 + tid) >> 3;       // local row
            int c = ((i * 256 + tid) & 7) << 2; // float col
            float* dst = &s_rows[r * RSTR + c];
            dst[0] = v.x; dst[1] = v.y; dst[2] = v.z; dst[3] = v.w;
        }
    }
    __syncthreads();

    // ---- gemv: fv[cin] from conflict-free LDS.32 ----
    unsigned long long acc[16];
#pragma unroll
    for (int q = 0; q < 16; q++) acc[q] = 0ull;
    {
        const float* myrow = &s_rows[tid * RSTR];
#pragma unroll
        for (int cin = 0; cin < 32; cin++) {
            unsigned long long bc;
            PACK2(bc, myrow[cin]);
            const ulonglong2* wv = (const ulonglong2*)(&w2[cin * 16]);
#pragma unroll
            for (int h = 0; h < 8; h++) {
                ulonglong2 wp = wv[h];
                FMA2(acc[2 * h],     bc, wp.x, acc[2 * h]);
                FMA2(acc[2 * h + 1], bc, wp.y, acc[2 * h + 1]);
            }
        }
    }

    float a[32];
#pragma unroll
    for (int h = 0; h < 16; h++) {
        unsigned int u0, u1;
        UNPACK2(u0, u1, acc[h]);
        a[2 * h]     = __uint_as_float(u0);
        a[2 * h + 1] = __uint_as_float(u1);
    }
    if (!act) {
#pragma unroll
        for (int i = 0; i < 32; i++) a[i] = 0.0f;
    }

    // add neighbor partials only where they exist (~25% of points)
    if (act && d_flag[pt]) {
        const float4* prow = (const float4*)(out + (long long)pt * CCH);
#pragma unroll
        for (int h = 0; h < 8; h++) {
            float4 p = __ldg(prow + h);
            a[4 * h + 0] += p.x;
            a[4 * h + 1] += p.y;
            a[4 * h + 2] += p.z;
            a[4 * h + 3] += p.w;
        }
    }

#pragma unroll
    for (int i = 0; i < 32; i++)
        a[i] = fmaxf(a[i], 0.01f * a[i]);

    // ---- BN butterfly (inactive threads contribute exact zeros) ----
    {
        float s[32], b[32];
#pragma unroll
        for (int i = 0; i < 32; i++) { s[i] = a[i]; b[i] = a[i] * a[i]; }
#pragma unroll
        for (int off = 16; off >= 1; off >>= 1) {
            bool hi = (lane & off) != 0;
#pragma unroll
            for (int i = 0; i < off; i++) {
                float sa = hi ? s[i] : s[i + off];
                float sb = hi ? b[i] : b[i + off];
                float ra = __shfl_xor_sync(0xffffffffu, sa, off);
                float rb = __shfl_xor_sync(0xffffffffu, sb, off);
                float ka = hi ? s[i + off] : s[i];
                float kb = hi ? b[i + off] : b[i];
                s[i] = ka + ra;
                b[i] = kb + rb;
            }
        }
        atomicAdd(&s_sum[lane], s[0]);
        atomicAdd(&s_sq[lane],  b[0]);
    }

    // ---- stage results back through smem, write coalesced ----
    __syncthreads();   // staging buffer reuse
    {
        float* dst = &s_rows[tid * RSTR];
#pragma unroll
        for (int i = 0; i < 32; i++) dst[i] = a[i];
    }
    __syncthreads();
    {
        float4* o4 = (float4*)out;
        int gbase = blk0 * 8;
#pragma unroll
        for (int i = 0; i < 8; i++) {
            int g = gbase + i * 256 + tid;
            if (g < NPTS * 8) {
                int r = (i * 256 + tid) >> 3;
                int c = ((i * 256 + tid) & 7) << 2;
                const float* src = &s_rows[r * RSTR + c];
                o4[g] = make_float4(src[0], src[1], src[2], src[3]);
            }
        }
    }

    if (tid < 32) {
        atomicAdd(&d_sums[tid],      s_sum[tid]);
        atomicAdd(&d_sums[32 + tid], s_sq[tid]);
    }
}

// ============================================================
// 5. finalize: scale/shift, re-zero accumulators for next replay
// ============================================================
__global__ void finalize_kernel(const float* __restrict__ gamma,
                                const float* __restrict__ beta) {
    int c = threadIdx.x;
    if (c < CCH) {
        const float invN = 1.0f / (float)NPTS;
        float mean = d_sums[c] * invN;
        float var  = d_sums[32 + c] * invN - mean * mean;
        float sc   = gamma[c] * rsqrtf(var + EPSV);
        d_scale[c] = sc;
        d_shift[c] = beta[c] - mean * sc;
        d_sums[c] = 0.0f;
        d_sums[32 + c] = 0.0f;
    }
}

// ============================================================
// 6. normalize in place: one thread per float4, coalesced
// ============================================================
__global__ void norm_kernel(float4* __restrict__ y) {
    int t = blockIdx.x * blockDim.x + threadIdx.x;
    if (t >= NPTS * 8) return;
    int q = (t & 7) * 4;
    float4 v = y[t];
    v.x = fmaf(v.x, d_scale[q + 0], d_shift[q + 0]);
    v.y = fmaf(v.y, d_scale[q + 1], d_shift[q + 1]);
    v.z = fmaf(v.z, d_scale[q + 2], d_shift[q + 2]);
    v.w = fmaf(v.w, d_scale[q + 3], d_shift[q + 3]);
    y[t] = v;
}

// ============================================================
extern "C" void kernel_launch(void* const* d_in, const int* in_sizes, int n_in,
                              void* d_out, int out_size) {
    const float* feat   = (const float*)d_in[0];
    const int4*  coords = (const int4*)d_in[1];
    const float* weight = (const float*)d_in[2];
    const float* gamma  = (const float*)d_in[3];
    const float* beta   = (const float*)d_in[4];
    float* out = (float*)d_out;

    prep_kernel<<<4096, 256>>>(coords, (float4*)out);
    probe_kernel<<<(NPTS + 255) / 256, 256>>>(coords);
    neighbor_kernel<<<dim3(64, 8), 256>>>(feat, weight, out);
    selfleaky_kernel<<<(NPTS + 255) / 256, 256>>>(feat, weight, out);
    finalize_kernel<<<1, 32>>>(gamma, beta);
    norm_kernel<<<(NPTS * 8 + 255) / 256, 256>>>((float4*)out);
}

// round 6
// speedup vs baseline: 1.4209x; 1.0571x over previous
#include <cuda_runtime.h>
#include <cstdint>

#define NPTS 400000
#define CCH  32
#define SX   480
#define SY   360
#define SZ   32
#define BB   2
#define LOOKUP_SIZE (BB*SX*SY*SZ)
#define EPSV 1e-5f

// ---- static scratch (no allocations allowed) ----
__device__ int   d_lookup[LOOKUP_SIZE];          // cell -> idx+1, 0 = empty (persistent)
__device__ __align__(16) float d_sums[64];       // [0:32) sum, [32:64) sumsq
__device__ float d_scale[CCH];
__device__ float d_shift[CCH];
__device__ int   d_cnt[8];                       // per-k pair counts (k != 4)
__device__ int2  d_pairs[8][NPTS];               // (out_pt, in_pt) per k
__device__ unsigned char d_flag[NPTS];           // point has >=1 valid neighbor

// ---- packed fp32x2 helpers ----
#define FMA2(d, a, b, c) \
    asm("fma.rn.f32x2 %0, %1, %2, %3;" : "=l"(d) : "l"(a), "l"(b), "l"(c))
#define PACK2(d, x) \
    asm("mov.b64 %0, {%1, %1};" : "=l"(d) : "r"(__float_as_uint(x)))
#define UNPACK2(lo, hi, a) \
    asm("mov.b64 {%0, %1}, %2;" : "=r"(lo), "=r"(hi) : "l"(a))

// ============================================================
// GEMV core from global feat row (used by neighbor kernel)
// ============================================================
__device__ __forceinline__ void gemv_accum(
    const float* __restrict__ frow,
    const unsigned long long* __restrict__ wbase,
    unsigned long long acc[16])
{
    const float4* fr = (const float4*)frow;
    float4 f0 = __ldg(fr + 0), f1 = __ldg(fr + 1);
    float4 f2 = __ldg(fr + 2), f3 = __ldg(fr + 3);
    float4 f4 = __ldg(fr + 4), f5 = __ldg(fr + 5);
    float4 f6 = __ldg(fr + 6), f7 = __ldg(fr + 7);
    float fv[32] = {
        f0.x, f0.y, f0.z, f0.w, f1.x, f1.y, f1.z, f1.w,
        f2.x, f2.y, f2.z, f2.w, f3.x, f3.y, f3.z, f3.w,
        f4.x, f4.y, f4.z, f4.w, f5.x, f5.y, f5.z, f5.w,
        f6.x, f6.y, f6.z, f6.w, f7.x, f7.y, f7.z, f7.w };
#pragma unroll
    for (int cin = 0; cin < 32; cin++) {
        unsigned long long bc;
        PACK2(bc, fv[cin]);
        const ulonglong2* wv = (const ulonglong2*)(wbase + cin * 16);
#pragma unroll
        for (int h = 0; h < 8; h++) {
            ulonglong2 wp = wv[h];
            FMA2(acc[2 * h],     bc, wp.x, acc[2 * h]);
            FMA2(acc[2 * h + 1], bc, wp.y, acc[2 * h + 1]);
        }
    }
}

// ============================================================
// 1. prep: reset pair counters + scatter lookup (no bulk zero)
// ============================================================
__global__ void prep_kernel(const int4* __restrict__ coords) {
    int i = blockIdx.x * blockDim.x + threadIdx.x;
    if (i < 8) d_cnt[i] = 0;
    if (i < NPTS) {
        int4 c = coords[i];
        d_lookup[((c.x * SX + c.y) * SY + c.z) * SZ + c.w] = i + 1;
    }
}

// ============================================================
// 2. probe: per-k pair lists + flags + zero flagged out rows
//    (warp-cooperative: 32 lanes x 4B = one 128B line per row)
// ============================================================
__global__ __launch_bounds__(256) void probe_kernel(const int4* __restrict__ coords,
                                                    float* __restrict__ out) {
    __shared__ int s_wcnt[8][8];
    __shared__ int s_wbase[8][8];
    int tid  = threadIdx.x;
    int lane = tid & 31;
    int warp = tid >> 5;
    int pt = blockIdx.x * 256 + tid;
    bool act = pt < NPTS;

    int4 cc = act ? coords[pt] : make_int4(0, 1, 0, 1);
    int base = ((cc.x * SX + cc.y) * SY + cc.z) * SZ + cc.w;

    unsigned mask = 0;
    int nb[8];
#pragma unroll
    for (int k = 0; k < 9; k++) {
        if (k == 4) continue;
        int d0 = k / 3 - 1, d2 = k % 3 - 1;
        int n0 = cc.y + d0, n2 = cc.w + d2;
        bool valid = act && (n0 >= 0) && (n0 < SX) && (n2 >= 0) && (n2 < SZ);
        int idx = valid ? (base + d0 * (SY * SZ) + d2) : 0;
        int j = valid ? __ldg(&d_lookup[idx]) : 0;
        int ki = (k < 4) ? k : k - 1;
        nb[ki] = j - 1;
        if (j > 0) mask |= (1u << ki);
    }

    if (act) d_flag[pt] = (unsigned char)(mask ? 1 : 0);

    // cooperative zero of flagged rows (these receive red.adds)
    {
        unsigned fb = __ballot_sync(0xffffffffu, act && mask);
        int wbase_pt = blockIdx.x * 256 + warp * 32;
        while (fb) {
            int p = __ffs(fb) - 1;
            fb &= fb - 1;
            out[(long long)(wbase_pt + p) * CCH + lane] = 0.0f;
        }
    }

    unsigned bal[8];
#pragma unroll
    for (int ki = 0; ki < 8; ki++)
        bal[ki] = __ballot_sync(0xffffffffu, (mask >> ki) & 1u);
    if (lane == 0) {
#pragma unroll
        for (int ki = 0; ki < 8; ki++)
            s_wcnt[ki][warp] = __popc(bal[ki]);
    }
    __syncthreads();
    if (tid < 8) {
        int run = 0;
#pragma unroll
        for (int w = 0; w < 8; w++) {
            int c = s_wcnt[tid][w];
            s_wbase[tid][w] = run;
            run += c;
        }
        int g = atomicAdd(&d_cnt[tid], run);
#pragma unroll
        for (int w = 0; w < 8; w++)
            s_wbase[tid][w] += g;
    }
    __syncthreads();
#pragma unroll
    for (int ki = 0; ki < 8; ki++) {
        if ((mask >> ki) & 1u) {
            int rank = __popc(bal[ki] & ((1u << lane) - 1u));
            d_pairs[ki][s_wbase[ki][warp] + rank] = make_int2(pt, nb[ki]);
        }
    }
}

// ============================================================
// 3. neighbor conv: grid.y = ki, one thread per pair, uniform-k
// ============================================================
__global__ __launch_bounds__(256) void neighbor_kernel(
    const float* __restrict__ feat,
    const float* __restrict__ weight,
    float*       __restrict__ out)
{
    int ki = blockIdx.y;
    int k  = (ki < 4) ? ki : ki + 1;
    __shared__ unsigned long long w2[512];
    {
        const unsigned long long* ws =
            (const unsigned long long*)(weight + k * 1024);
        for (int i = threadIdx.x; i < 512; i += 256)
            w2[i] = ws[i];
    }
    __syncthreads();

    int n = d_cnt[ki];
    for (int p = blockIdx.x * 256 + threadIdx.x; p < n; p += gridDim.x * 256) {
        int2 pr = d_pairs[ki][p];
        unsigned long long acc[16];
#pragma unroll
        for (int q = 0; q < 16; q++) acc[q] = 0ull;
        gemv_accum(feat + (long long)pr.y * CCH, w2, acc);

        float* orow = out + (long long)pr.x * CCH;
#pragma unroll
        for (int h = 0; h < 8; h++) {
            unsigned int u0, u1, u2, u3;
            UNPACK2(u0, u1, acc[2 * h]);
            UNPACK2(u2, u3, acc[2 * h + 1]);
            asm volatile("red.global.add.v4.f32 [%0], {%1, %2, %3, %4};"
                         :: "l"(orow + 4 * h),
                            "f"(__uint_as_float(u0)), "f"(__uint_as_float(u1)),
                            "f"(__uint_as_float(u2)), "f"(__uint_as_float(u3))
                         : "memory");
        }
    }
}

// ============================================================
// 4. self conv + partial add + LeakyReLU + BN reduce
//    split-cout register tiling: thread = 16 couts x 2 points
//    weights LDS amortized 4x; BN fused into coalesced writeback
// ============================================================
#define RSTR 33
#define BPTS 256
__global__ __launch_bounds__(256, 3) void selfleaky_kernel(
    const float* __restrict__ feat,
    const float* __restrict__ weight,
    float*       __restrict__ out)
{
    __shared__ float s_rows[BPTS * RSTR];        // 33.8 KB staging (in, then out)
    __shared__ unsigned long long w2[512];       // 4 KB weights (k=4)
    __shared__ unsigned char s_flag[BPTS];
    __shared__ float s_sum[32], s_sq[32];

    int tid  = threadIdx.x;
    int blk0 = blockIdx.x * BPTS;

    {
        const unsigned long long* ws =
            (const unsigned long long*)(weight + 4 * 1024);
        for (int i = tid; i < 512; i += 256)
            w2[i] = ws[i];
        if (tid < 32) { s_sum[tid] = 0.0f; s_sq[tid] = 0.0f; }
    }

    // ---- stage 256 feature rows + flags, coalesced ----
    {
        const float4* f4 = (const float4*)feat;
        int gbase = blk0 * 8;
#pragma unroll
        for (int i = 0; i < 8; i++) {
            int idx = i * 256 + tid;
            int g = gbase + idx;
            float4 v = (g < NPTS * 8) ? __ldg(f4 + g)
                                      : make_float4(0.f, 0.f, 0.f, 0.f);
            int r = idx >> 3;
            int c = (idx & 7) << 2;
            float* dst = &s_rows[r * RSTR + c];
            dst[0] = v.x; dst[1] = v.y; dst[2] = v.z; dst[3] = v.w;
        }
        int p = blk0 + tid;
        s_flag[tid] = (p < NPTS) ? d_flag[p] : 0;
    }
    __syncthreads();

    // ---- register-tiled GEMM: 16 couts x 2 points per thread ----
    int half = tid >> 7;          // cout half: couts [16*half, 16*half+16)
    int i0   = tid & 127;         // point slot: points i0, i0+128

    unsigned long long acc[16];   // [j*8 + h], j=point, h=cout f32x2 pair
#pragma unroll
    for (int q = 0; q < 16; q++) acc[q] = 0ull;

    {
        const ulonglong2* wv = (const ulonglong2*)&w2[8 * half];
        const float* r0 = &s_rows[i0 * RSTR];
        const float* r1 = &s_rows[(i0 + 128) * RSTR];
#pragma unroll 4
        for (int cin = 0; cin < 32; cin++) {
            ulonglong2 wa = wv[cin * 8 + 0];
            ulonglong2 wb = wv[cin * 8 + 1];
            ulonglong2 wc = wv[cin * 8 + 2];
            ulonglong2 wd = wv[cin * 8 + 3];
            unsigned long long b0, b1;
            PACK2(b0, r0[cin]);
            PACK2(b1, r1[cin]);
            FMA2(acc[0], b0, wa.x, acc[0]);
            FMA2(acc[1], b0, wa.y, acc[1]);
            FMA2(acc[2], b0, wb.x, acc[2]);
            FMA2(acc[3], b0, wb.y, acc[3]);
            FMA2(acc[4], b0, wc.x, acc[4]);
            FMA2(acc[5], b0, wc.y, acc[5]);
            FMA2(acc[6], b0, wd.x, acc[6]);
            FMA2(acc[7], b0, wd.y, acc[7]);
            FMA2(acc[8],  b1, wa.x, acc[8]);
            FMA2(acc[9],  b1, wa.y, acc[9]);
            FMA2(acc[10], b1, wb.x, acc[10]);
            FMA2(acc[11], b1, wb.y, acc[11]);
            FMA2(acc[12], b1, wc.x, acc[12]);
            FMA2(acc[13], b1, wc.y, acc[13]);
            FMA2(acc[14], b1, wd.x, acc[14]);
            FMA2(acc[15], b1, wd.y, acc[15]);
        }
    }
    __syncthreads();   // everyone done reading s_rows

    // ---- write conv outputs back into s_rows (same layout) ----
#pragma unroll
    for (int j = 0; j < 2; j++) {
        float* dst = &s_rows[(i0 + 128 * j) * RSTR + 16 * half];
#pragma unroll
        for (int h = 0; h < 8; h++) {
            unsigned int u0, u1;
            UNPACK2(u0, u1, acc[j * 8 + h]);
            dst[2 * h]     = __uint_as_float(u0);
            dst[2 * h + 1] = __uint_as_float(u1);
        }
    }
    __syncthreads();

    // ---- fused writeback: +partials, leaky, store, BN accumulate ----
    float bs0 = 0.f, bs1 = 0.f, bs2 = 0.f, bs3 = 0.f;
    float bq0 = 0.f, bq1 = 0.f, bq2 = 0.f, bq3 = 0.f;
    {
        float4* o4 = (float4*)out;
        int gbase = blk0 * 8;
#pragma unroll
        for (int i = 0; i < 8; i++) {
            int idx = i * 256 + tid;
            int g = gbase + idx;
            if (g < NPTS * 8) {
                int r = idx >> 3;
                int c = (idx & 7) << 2;
                const float* src = &s_rows[r * RSTR + c];
                float4 v = make_float4(src[0], src[1], src[2], src[3]);
                if (s_flag[r]) {
                    float4 p = __ldg(o4 + g);
                    v.x += p.x; v.y += p.y; v.z += p.z; v.w += p.w;
                }
                v.x = fmaxf(v.x, 0.01f * v.x);
                v.y = fmaxf(v.y, 0.01f * v.y);
                v.z = fmaxf(v.z, 0.01f * v.z);
                v.w = fmaxf(v.w, 0.01f * v.w);
                o4[g] = v;
                bs0 += v.x; bq0 = fmaf(v.x, v.x, bq0);
                bs1 += v.y; bq1 = fmaf(v.y, v.y, bq1);
                bs2 += v.z; bq2 = fmaf(v.z, v.z, bq2);
                bs3 += v.w; bq3 = fmaf(v.w, v.w, bq3);
            }
        }
    }
    {
        int c0 = (tid & 7) * 4;   // fixed channel quad for this thread
        atomicAdd(&s_sum[c0 + 0], bs0);
        atomicAdd(&s_sum[c0 + 1], bs1);
        atomicAdd(&s_sum[c0 + 2], bs2);
        atomicAdd(&s_sum[c0 + 3], bs3);
        atomicAdd(&s_sq[c0 + 0], bq0);
        atomicAdd(&s_sq[c0 + 1], bq1);
        atomicAdd(&s_sq[c0 + 2], bq2);
        atomicAdd(&s_sq[c0 + 3], bq3);
    }
    __syncthreads();
    if (tid < 32) {
        atomicAdd(&d_sums[tid],      s_sum[tid]);
        atomicAdd(&d_sums[32 + tid], s_sq[tid]);
    }
}

// ============================================================
// 5. finalize: scale/shift, re-zero accumulators for next replay
// ============================================================
__global__ void finalize_kernel(const float* __restrict__ gamma,
                                const float* __restrict__ beta) {
    int c = threadIdx.x;
    if (c < CCH) {
        const float invN = 1.0f / (float)NPTS;
        float mean = d_sums[c] * invN;
        float var  = d_sums[32 + c] * invN - mean * mean;
        float sc   = gamma[c] * rsqrtf(var + EPSV);
        d_scale[c] = sc;
        d_shift[c] = beta[c] - mean * sc;
        d_sums[c] = 0.0f;
        d_sums[32 + c] = 0.0f;
    }
}

// ============================================================
// 6. normalize in place: 4 independent float4 per thread (MLP=4)
// ============================================================
__global__ __launch_bounds__(256) void norm_kernel(float4* __restrict__ y) {
    __shared__ float4 s_sc[8], s_sh[8];
    if (threadIdx.x < 8) {
        s_sc[threadIdx.x] = ((const float4*)d_scale)[threadIdx.x];
        s_sh[threadIdx.x] = ((const float4*)d_shift)[threadIdx.x];
    }
    __syncthreads();
    int base = blockIdx.x * 1024;
#pragma unroll
    for (int i = 0; i < 4; i++) {
        int t = base + i * 256 + threadIdx.x;
        if (t < NPTS * 8) {
            int q = t & 7;
            float4 v = y[t];
            float4 sc = s_sc[q], sh = s_sh[q];
            v.x = fmaf(v.x, sc.x, sh.x);
            v.y = fmaf(v.y, sc.y, sh.y);
            v.z = fmaf(v.z, sc.z, sh.z);
            v.w = fmaf(v.w, sc.w, sh.w);
            y[t] = v;
        }
    }
}

// ============================================================
extern "C" void kernel_launch(void* const* d_in, const int* in_sizes, int n_in,
                              void* d_out, int out_size) {
    const float* feat   = (const float*)d_in[0];
    const int4*  coords = (const int4*)d_in[1];
    const float* weight = (const float*)d_in[2];
    const float* gamma  = (const float*)d_in[3];
    const float* beta   = (const float*)d_in[4];
    float* out = (float*)d_out;

    prep_kernel<<<(NPTS + 255) / 256, 256>>>(coords);
    probe_kernel<<<(NPTS + 255) / 256, 256>>>(coords, out);
    neighbor_kernel<<<dim3(64, 8), 256>>>(feat, weight, out);
    selfleaky_kernel<<<(NPTS + 255) / 256, 256>>>(feat, weight, out);
    finalize_kernel<<<1, 32>>>(gamma, beta);
    norm_kernel<<<(NPTS * 8 + 1023) / 1024, 256>>>((float4*)out);
}